// round 12
// baseline (speedup 1.0000x reference)
#include <cuda_runtime.h>
#include <math.h>
#include <stdint.h>

// Problem constants
#define N_IMG     16
#define N_CH      3
#define NSLICE    (N_IMG * N_CH)          // 48
#define BINS      64
#define SLICE_ELEMS (1024 * 1024)

#define HTHREADS  128
#define BPS       18                              // 864 blocks (one wave at occ 6)
#define NBLOCKS   (NSLICE * BPS)
// Two u32 arrays [32][128]; each word packs 2 bins (lo = even bin, hi = odd bin)
#define WORDS_PER_ARR (32 * HTHREADS)             // 4096
#define HSMEM_WORDS   (2 * WORDS_PER_ARR)         // 8192
#define HSMEM_BYTES   (HSMEM_WORDS * 4)           // 32 KB

// Params layout (in_ch,out_ch row-major), per reference
#define P_W1 0
#define P_B1 24576
#define P_W2 24704
#define P_B2 28800
#define P_G  28832

__device__ float g_part[NBLOCKS * BINS];

__global__ __launch_bounds__(HTHREADS, 6)
void hist_kernel(const float* __restrict__ img) {
    extern __shared__ unsigned int hh[];   // A = hh[0..4095], B = hh[4096..8191]
    const int tid = threadIdx.x;

    const int slice = blockIdx.x / BPS;
    const int chunk = blockIdx.x % BPS;
    const float4* base = reinterpret_cast<const float4*>(img + (size_t)slice * SLICE_ELEMS);
    const int n4   = SLICE_ELEMS / 4;                 // 262144
    const int per  = (n4 + BPS - 1) / BPS;            // 14564
    const int start = chunk * per;
    const int end   = min(start + per, n4);

    // ---- Prefetch FIRST batch before zeroing: loads fly during the prolog ----
    int i = start + tid;
    float4 A[4], B[4];
    bool hasA = (i + 3 * HTHREADS < end);
    if (hasA) {
        #pragma unroll
        for (int u = 0; u < 4; u++) A[u] = __ldcs(base + i + u * HTHREADS);
    }

    // zero both counter arrays while LDGs are in flight
    {
        uint4* z = reinterpret_cast<uint4*>(hh);
        #pragma unroll
        for (int q = tid; q < HSMEM_WORDS / 4; q += HTHREADS)
            z[q] = make_uint4(0u, 0u, 0u, 0u);
    }
    __syncthreads();

    unsigned int* pA = hh + tid;                       // word (b>>1): pA[(b>>1)*128]
    unsigned int* pB = hh + WORDS_PER_ARR + tid;

    // Full-word RMW, word owned by one thread. inc = 1 or 65536 by bin parity.
    // __fmul_rd keeps bin <= 63 for v in [0,1).
#define PROCPAIR(vA, vB) { \
        int ba = (int)__fmul_rd((vA), 64.0f); \
        int bb = (int)__fmul_rd((vB), 64.0f); \
        unsigned int incA = 1u << ((ba & 1) << 4); \
        unsigned int incB = 1u << ((bb & 1) << 4); \
        unsigned int ca = pA[(ba >> 1) * HTHREADS]; \
        unsigned int cb = pB[(bb >> 1) * HTHREADS]; \
        pA[(ba >> 1) * HTHREADS] = ca + incA; \
        pB[(bb >> 1) * HTHREADS] = cb + incB; }
#define PROC(v4) { PROCPAIR((v4).x, (v4).y); PROCPAIR((v4).z, (v4).w); }

    while (hasA) {
        const int j = i + 4 * HTHREADS;
        const bool hasB = (j + 3 * HTHREADS < end);
        if (hasB) {
            #pragma unroll
            for (int u = 0; u < 4; u++) B[u] = __ldcs(base + j + u * HTHREADS);
        }
        #pragma unroll
        for (int u = 0; u < 4; u++) PROC(A[u]);
        i = j;
        if (!hasB) break;
        const int k = j + 4 * HTHREADS;
        hasA = (k + 3 * HTHREADS < end);
        if (hasA) {
            #pragma unroll
            for (int u = 0; u < 4; u++) A[u] = __ldcs(base + k + u * HTHREADS);
        }
        #pragma unroll
        for (int u = 0; u < 4; u++) PROC(B[u]);
        i = k;
    }
    for (; i < end; i += HTHREADS) {
        float4 a = __ldcs(base + i);
        PROC(a);
    }
#undef PROC
#undef PROCPAIR
    __syncthreads();

    // Epilogue: warp w (of 4) reduces words 8w..8w+7 across 128 cols x 2 arrays.
    // Packed sums <= 58368 per halfword -> no carry between halves.
    const int wid  = tid >> 5;
    const int lane = tid & 31;
    #pragma unroll
    for (int r = 0; r < 8; r++) {
        const int wd = wid * 8 + r;
        const unsigned int* ra = hh + wd * HTHREADS;
        const unsigned int* rb = hh + WORDS_PER_ARR + wd * HTHREADS;
        unsigned int s = ra[lane] + ra[lane + 32] + ra[lane + 64] + ra[lane + 96]
                       + rb[lane] + rb[lane + 32] + rb[lane + 64] + rb[lane + 96];
        #pragma unroll
        for (int d = 16; d >= 1; d >>= 1)
            s += __shfl_down_sync(0xFFFFFFFFu, s, d);
        if (lane == 0) {
            g_part[blockIdx.x * BINS + 2 * wd]     = (float)(s & 0xFFFFu);
            g_part[blockIdx.x * BINS + 2 * wd + 1] = (float)(s >> 16);
        }
    }
}

// MLP with PDL: grid=16 (one image per block), 256 threads.
#define MLP_BLOCKS  16
#define MLP_THREADS 256
#define MLP_SMEM_FLOATS (24576 + 4096 + 192 + 256 + 128 + 128)
#define MLP_SMEM_BYTES  (MLP_SMEM_FLOATS * 4)

__global__ __launch_bounds__(MLP_THREADS, 1)
void mlp_kernel(const float* __restrict__ params, float* __restrict__ out) {
    extern __shared__ float smem[];
    float* s_w1   = smem;                 // [192][128]
    float* s_w2   = s_w1 + 24576;         // [128][32]
    float* s_hist = s_w2 + 4096;          // [192]
    float* s_p1   = s_hist + 192;         // [2][128]
    float* s_h1   = s_p1 + 256;           // [128]
    float* s_l2   = s_h1 + 128;           // [4][32]

    const int tid = threadIdx.x;
    const int n   = blockIdx.x;

    // Pre-sync: stage weights (overlaps with hist via PDL)
    #pragma unroll
    for (int i = tid; i < 24576 / 4; i += MLP_THREADS)
        reinterpret_cast<float4*>(s_w1)[i] = reinterpret_cast<const float4*>(params + P_W1)[i];
    #pragma unroll
    for (int i = tid; i < 4096 / 4; i += MLP_THREADS)
        reinterpret_cast<float4*>(s_w2)[i] = reinterpret_cast<const float4*>(params + P_W2)[i];

    cudaGridDependencySynchronize();

    if (tid < 192) {
        int c = tid >> 6;
        int b = tid & 63;
        const float* p = g_part + ((n * 3 + c) * BPS) * BINS + b;
        float s = 0.0f;
        #pragma unroll
        for (int k = 0; k < BPS; k++) s += p[k * BINS];
        s_hist[tid] = s;
    }
    __syncthreads();

    {
        const int j    = tid & 127;
        const int half = tid >> 7;
        const int c0   = half * 96;
        float acc = 0.0f;
        #pragma unroll 16
        for (int c = c0; c < c0 + 96; c++)
            acc = fmaf(s_hist[c], s_w1[c * 128 + j], acc);
        s_p1[half * 128 + j] = acc;
    }
    __syncthreads();
    if (tid < 128)
        s_h1[tid] = fmaxf(s_p1[tid] + s_p1[128 + tid] + params[P_B1 + tid], 0.0f);
    __syncthreads();

    if (tid < 128) {
        const int q = tid >> 5;
        const int k = tid & 31;
        float a = 0.0f;
        #pragma unroll
        for (int c = q * 32; c < q * 32 + 32; c++)
            a = fmaf(s_h1[c], s_w2[c * 32 + k], a);
        s_l2[tid] = a;
    }
    __syncthreads();

    if (tid < 32) {
        float a = params[P_B2 + tid] + params[P_G]
                + s_l2[tid] + s_l2[32 + tid] + s_l2[64 + tid] + s_l2[96 + tid];
        out[n * 32 + tid] = 1.0f / (1.0f + expf(-a));
    }
}

extern "C" void kernel_launch(void* const* d_in, const int* in_sizes, int n_in,
                              void* d_out, int out_size) {
    const float* img    = (const float*)d_in[0];
    const float* params = (const float*)d_in[1];
    float* out          = (float*)d_out;

    static bool attr_set = false;
    if (!attr_set) {
        cudaFuncSetAttribute(hist_kernel, cudaFuncAttributeMaxDynamicSharedMemorySize, HSMEM_BYTES);
        cudaFuncSetAttribute(mlp_kernel,  cudaFuncAttributeMaxDynamicSharedMemorySize, MLP_SMEM_BYTES);
        attr_set = true;
    }

    hist_kernel<<<NBLOCKS, HTHREADS, HSMEM_BYTES>>>(img);

    cudaLaunchConfig_t cfg = {};
    cfg.gridDim  = dim3(MLP_BLOCKS, 1, 1);
    cfg.blockDim = dim3(MLP_THREADS, 1, 1);
    cfg.dynamicSmemBytes = MLP_SMEM_BYTES;
    cudaLaunchAttribute attrs[1];
    attrs[0].id = cudaLaunchAttributeProgrammaticStreamSerialization;
    attrs[0].val.programmaticStreamSerializationAllowed = 1;
    cfg.attrs = attrs;
    cfg.numAttrs = 1;
    cudaLaunchKernelEx(&cfg, mlp_kernel, params, out);
}

// round 13
// speedup vs baseline: 1.1276x; 1.1276x over previous
#include <cuda_runtime.h>
#include <math.h>
#include <stdint.h>

// Problem constants
#define N_IMG     16
#define N_CH      3
#define NSLICE    (N_IMG * N_CH)          // 48
#define BINS      64
#define SLICE_ELEMS (1024 * 1024)

#define HTHREADS  128
#define BPS       9                               // 432 blocks (one wave at occ 3)
#define NBLOCKS   (NSLICE * BPS)
// Two u32 counter arrays [64][128] = 32 KB each
#define HSMEM_WORDS (2 * BINS * HTHREADS)
#define HSMEM_BYTES (HSMEM_WORDS * 4)             // 64 KB

// Params layout (in_ch,out_ch row-major), per reference
#define P_W1 0
#define P_B1 24576
#define P_W2 24704
#define P_B2 28800
#define P_G  28832
#define P_TOTAL 28833

__device__ float g_part[NBLOCKS * BINS];

__global__ __launch_bounds__(HTHREADS, 3)
void hist_kernel(const float* __restrict__ img) {
    extern __shared__ unsigned int hh[];   // A = hh[0..8191], B = hh[8192..16383]
    const int tid = threadIdx.x;

    const int slice = blockIdx.x / BPS;
    const int chunk = blockIdx.x % BPS;
    const float4* base = reinterpret_cast<const float4*>(img + (size_t)slice * SLICE_ELEMS);
    const int n4   = SLICE_ELEMS / 4;                 // 262144
    const int per  = (n4 + BPS - 1) / BPS;            // 29128
    const int start = chunk * per;
    const int end   = min(start + per, n4);

    // ---- Prefetch FIRST batch before zeroing: loads fly during the prolog ----
    int i = start + tid;
    float4 A[8], B[8];
    bool hasA = (i + 7 * HTHREADS < end);
    if (hasA) {
        #pragma unroll
        for (int u = 0; u < 8; u++) A[u] = __ldcs(base + i + u * HTHREADS);
    }

    {
        uint4* z = reinterpret_cast<uint4*>(hh);
        #pragma unroll
        for (int q = tid; q < HSMEM_WORDS / 4; q += HTHREADS)
            z[q] = make_uint4(0u, 0u, 0u, 0u);
    }
    __syncthreads();

    unsigned int* pA = hh + tid;                       // A[b][tid] at pA[b*128]
    unsigned int* pB = hh + BINS * HTHREADS + tid;     // B[b][tid] at pB[b*128]

#define PROCPAIR(vA, vB) { \
        int ba = (int)__fmul_rd((vA), 64.0f); \
        int bb = (int)__fmul_rd((vB), 64.0f); \
        unsigned int ca = pA[ba * HTHREADS]; \
        unsigned int cb = pB[bb * HTHREADS]; \
        pA[ba * HTHREADS] = ca + 1u; \
        pB[bb * HTHREADS] = cb + 1u; }
#define PROC(v4) { PROCPAIR((v4).x, (v4).y); PROCPAIR((v4).z, (v4).w); }

    while (hasA) {
        const int j = i + 8 * HTHREADS;
        const bool hasB = (j + 7 * HTHREADS < end);
        if (hasB) {
            #pragma unroll
            for (int u = 0; u < 8; u++) B[u] = __ldcs(base + j + u * HTHREADS);
        }
        #pragma unroll
        for (int u = 0; u < 8; u++) PROC(A[u]);
        i = j;
        if (!hasB) break;
        const int k = j + 8 * HTHREADS;
        hasA = (k + 7 * HTHREADS < end);
        if (hasA) {
            #pragma unroll
            for (int u = 0; u < 8; u++) A[u] = __ldcs(base + k + u * HTHREADS);
        }
        #pragma unroll
        for (int u = 0; u < 8; u++) PROC(B[u]);
        i = k;
    }
    for (; i < end; i += HTHREADS) {
        float4 a = __ldcs(base + i);
        PROC(a);
    }
#undef PROC
#undef PROCPAIR
    __syncthreads();

    // Epilogue: warp w (of 4) reduces bins 16w..16w+15 over 128 columns x 2 arrays.
    const int wid  = tid >> 5;
    const int lane = tid & 31;
    #pragma unroll
    for (int r = 0; r < 16; r++) {
        const int b = wid * 16 + r;
        const unsigned int* ra = hh + b * HTHREADS;
        const unsigned int* rb = hh + BINS * HTHREADS + b * HTHREADS;
        unsigned int s = ra[lane] + ra[lane + 32] + ra[lane + 64] + ra[lane + 96]
                       + rb[lane] + rb[lane + 32] + rb[lane + 64] + rb[lane + 96];
        #pragma unroll
        for (int d = 16; d >= 1; d >>= 1)
            s += __shfl_down_sync(0xFFFFFFFFu, s, d);
        if (lane == 0)
            g_part[blockIdx.x * BINS + b] = (float)s;
    }
}

// MLP with PDL: grid=16 (one image/block), 128 threads, ~3 KB smem so blocks
// CO-RESIDE with hist (hist leaves 36 KB smem + 12 block-slots free).
// Pre-sync: prefetch params into L2 (discard-sum). Post-sync: read weights from L2.
#define MLP_BLOCKS  16
#define MLP_THREADS 128
#define MLP_SMEM_FLOATS (192 + 128 + 128 + 4)
#define MLP_SMEM_BYTES  (MLP_SMEM_FLOATS * 4)

__global__ __launch_bounds__(MLP_THREADS, 1)
void mlp_kernel(const float* __restrict__ params, float* __restrict__ out) {
    extern __shared__ float smem[];
    float* s_hist = smem;                 // [192]
    float* s_h1   = s_hist + 192;         // [128]
    float* s_l2   = s_h1 + 128;           // [128]
    float* s_dump = s_l2 + 128;           // [4] DCE-guard sink

    const int tid = threadIdx.x;
    const int n   = blockIdx.x;

    // ---- Pre-sync: warm L2 with all params (runs during hist) ----
    {
        const float4* p4 = reinterpret_cast<const float4*>(params);
        const int n4 = P_TOTAL / 4;   // 7208
        float4 acc = make_float4(0.f, 0.f, 0.f, 0.f);
        for (int i = tid; i < n4; i += MLP_THREADS) {
            float4 v = __ldg(p4 + i);
            acc.x += v.x; acc.y += v.y; acc.z += v.z; acc.w += v.w;
        }
        // opaque guard: never true at runtime, unknowable at compile time
        if (reinterpret_cast<uintptr_t>(out) == 1)
            s_dump[0] = acc.x + acc.y + acc.z + acc.w;
    }

    cudaGridDependencySynchronize();

    // Reduce per-chunk partials for this image (g_part is L2-hot)
    for (int c2 = tid; c2 < 192; c2 += MLP_THREADS) {
        int c = c2 >> 6;
        int b = c2 & 63;
        const float* p = g_part + ((n * 3 + c) * BPS) * BINS + b;
        float s = 0.0f;
        #pragma unroll
        for (int k = 0; k < BPS; k++) s += p[k * BINS];
        s_hist[c2] = s;
    }
    __syncthreads();

    // Layer 1: thread j computes h1[j]; W1 read from L2 (coalesced across j)
    {
        const int j = tid;
        float acc = __ldg(params + P_B1 + j);
        #pragma unroll 8
        for (int c = 0; c < 192; c++)
            acc = fmaf(s_hist[c], __ldg(params + P_W1 + c * 128 + j), acc);
        s_h1[j] = fmaxf(acc, 0.0f);
    }
    __syncthreads();

    // Layer 2: quarter q = tid>>5 sums c in [q*32, q*32+32) for output k = tid&31
    {
        const int q = tid >> 5;
        const int k = tid & 31;
        float a = 0.0f;
        #pragma unroll
        for (int c = q * 32; c < q * 32 + 32; c++)
            a = fmaf(s_h1[c], __ldg(params + P_W2 + c * 32 + k), a);
        s_l2[tid] = a;
    }
    __syncthreads();

    if (tid < 32) {
        float a = __ldg(params + P_B2 + tid) + __ldg(params + P_G)
                + s_l2[tid] + s_l2[32 + tid] + s_l2[64 + tid] + s_l2[96 + tid];
        out[n * 32 + tid] = 1.0f / (1.0f + expf(-a));
    }
}

extern "C" void kernel_launch(void* const* d_in, const int* in_sizes, int n_in,
                              void* d_out, int out_size) {
    const float* img    = (const float*)d_in[0];
    const float* params = (const float*)d_in[1];
    float* out          = (float*)d_out;

    static bool attr_set = false;
    if (!attr_set) {
        cudaFuncSetAttribute(hist_kernel, cudaFuncAttributeMaxDynamicSharedMemorySize, HSMEM_BYTES);
        cudaFuncSetAttribute(mlp_kernel,  cudaFuncAttributeMaxDynamicSharedMemorySize, MLP_SMEM_BYTES);
        attr_set = true;
    }

    hist_kernel<<<NBLOCKS, HTHREADS, HSMEM_BYTES>>>(img);

    cudaLaunchConfig_t cfg = {};
    cfg.gridDim  = dim3(MLP_BLOCKS, 1, 1);
    cfg.blockDim = dim3(MLP_THREADS, 1, 1);
    cfg.dynamicSmemBytes = MLP_SMEM_BYTES;
    cudaLaunchAttribute attrs[1];
    attrs[0].id = cudaLaunchAttributeProgrammaticStreamSerialization;
    attrs[0].val.programmaticStreamSerializationAllowed = 1;
    cfg.attrs = attrs;
    cfg.numAttrs = 1;
    cudaLaunchKernelEx(&cfg, mlp_kernel, params, out);
}

// round 14
// speedup vs baseline: 1.1546x; 1.0239x over previous
#include <cuda_runtime.h>
#include <math.h>
#include <stdint.h>

// Problem constants
#define N_IMG     16
#define N_CH      3
#define NSLICE    (N_IMG * N_CH)          // 48
#define BINS      64
#define SLICE_ELEMS (1024 * 1024)

#define HTHREADS  128
#define BPS       9                               // 432 blocks (one wave at occ 3)
#define NBLOCKS   (NSLICE * BPS)
// Two u32 counter arrays [64][128] = 32 KB each
#define HSMEM_WORDS (2 * BINS * HTHREADS)
#define HSMEM_BYTES (HSMEM_WORDS * 4)             // 64 KB

// Params layout (in_ch,out_ch row-major), per reference
#define P_W1 0
#define P_B1 24576
#define P_W2 24704
#define P_B2 28800
#define P_G  28832

__device__ float g_part[NBLOCKS * BINS];
__device__ float g_h1[N_IMG * 128];

__global__ __launch_bounds__(HTHREADS, 3)
void hist_kernel(const float* __restrict__ img) {
    extern __shared__ unsigned int hh[];   // A = hh[0..8191], B = hh[8192..16383]
    const int tid = threadIdx.x;

    const int slice = blockIdx.x / BPS;
    const int chunk = blockIdx.x % BPS;
    const float4* base = reinterpret_cast<const float4*>(img + (size_t)slice * SLICE_ELEMS);
    const int n4   = SLICE_ELEMS / 4;                 // 262144
    const int per  = (n4 + BPS - 1) / BPS;            // 29128
    const int start = chunk * per;
    const int end   = min(start + per, n4);

    // Prefetch FIRST batch before zeroing: loads fly during the prolog
    int i = start + tid;
    float4 A[8], B[8];
    bool hasA = (i + 7 * HTHREADS < end);
    if (hasA) {
        #pragma unroll
        for (int u = 0; u < 8; u++) A[u] = __ldcs(base + i + u * HTHREADS);
    }

    {
        uint4* z = reinterpret_cast<uint4*>(hh);
        #pragma unroll
        for (int q = tid; q < HSMEM_WORDS / 4; q += HTHREADS)
            z[q] = make_uint4(0u, 0u, 0u, 0u);
    }
    __syncthreads();

    unsigned int* pA = hh + tid;
    unsigned int* pB = hh + BINS * HTHREADS + tid;

#define PROCPAIR(vA, vB) { \
        int ba = (int)__fmul_rd((vA), 64.0f); \
        int bb = (int)__fmul_rd((vB), 64.0f); \
        unsigned int ca = pA[ba * HTHREADS]; \
        unsigned int cb = pB[bb * HTHREADS]; \
        pA[ba * HTHREADS] = ca + 1u; \
        pB[bb * HTHREADS] = cb + 1u; }
#define PROC(v4) { PROCPAIR((v4).x, (v4).y); PROCPAIR((v4).z, (v4).w); }

    while (hasA) {
        const int j = i + 8 * HTHREADS;
        const bool hasB = (j + 7 * HTHREADS < end);
        if (hasB) {
            #pragma unroll
            for (int u = 0; u < 8; u++) B[u] = __ldcs(base + j + u * HTHREADS);
        }
        #pragma unroll
        for (int u = 0; u < 8; u++) PROC(A[u]);
        i = j;
        if (!hasB) break;
        const int k = j + 8 * HTHREADS;
        hasA = (k + 7 * HTHREADS < end);
        if (hasA) {
            #pragma unroll
            for (int u = 0; u < 8; u++) A[u] = __ldcs(base + k + u * HTHREADS);
        }
        #pragma unroll
        for (int u = 0; u < 8; u++) PROC(B[u]);
        i = k;
    }
    for (; i < end; i += HTHREADS) {
        float4 a = __ldcs(base + i);
        PROC(a);
    }
#undef PROC
#undef PROCPAIR
    __syncthreads();

    const int wid  = tid >> 5;
    const int lane = tid & 31;
    #pragma unroll
    for (int r = 0; r < 16; r++) {
        const int b = wid * 16 + r;
        const unsigned int* ra = hh + b * HTHREADS;
        const unsigned int* rb = hh + BINS * HTHREADS + b * HTHREADS;
        unsigned int s = ra[lane] + ra[lane + 32] + ra[lane + 64] + ra[lane + 96]
                       + rb[lane] + rb[lane + 32] + rb[lane + 64] + rb[lane + 96];
        #pragma unroll
        for (int d = 16; d >= 1; d >>= 1)
            s += __shfl_down_sync(0xFFFFFFFFu, s, d);
        if (lane == 0)
            g_part[blockIdx.x * BINS + b] = (float)s;
    }
}

// L1 kernel: 64 blocks = (image n = blk>>2, j-quarter q = blk&3), 128 threads.
// Stages its W1 quarter (24 KB) pre-sync -> co-resides with hist (36 KB/SM free).
#define L1_BLOCKS  (N_IMG * 4)
#define L1_THREADS 128
#define L1_SMEM_FLOATS (6144 + 192 + 128)
#define L1_SMEM_BYTES  (L1_SMEM_FLOATS * 4)       // ~25.9 KB

__global__ __launch_bounds__(L1_THREADS, 1)
void l1_kernel(const float* __restrict__ params) {
    extern __shared__ float sm1[];
    float* s_w1q  = sm1;            // [192][32] quarter columns
    float* s_hist = s_w1q + 6144;   // [192]
    float* s_p    = s_hist + 192;   // [4][32] partials

    const int tid = threadIdx.x;
    const int n   = blockIdx.x >> 2;
    const int q   = blockIdx.x & 3;

    // Pre-sync: stage W1 columns [q*32, q*32+32) for all 192 rows (overlaps hist)
    #pragma unroll 4
    for (int idx = tid; idx < 6144; idx += L1_THREADS) {
        int c  = idx >> 5;
        int jj = idx & 31;
        s_w1q[idx] = __ldg(params + P_W1 + c * 128 + q * 32 + jj);
    }

    cudaGridDependencySynchronize();

    // Reduce per-chunk partials for this image (g_part is L2-hot)
    for (int c2 = tid; c2 < 192; c2 += L1_THREADS) {
        int c = c2 >> 6;
        int b = c2 & 63;
        const float* p = g_part + ((n * 3 + c) * BPS) * BINS + b;
        float s = 0.0f;
        #pragma unroll
        for (int k = 0; k < BPS; k++) s += p[k * BINS];
        s_hist[c2] = s;
    }
    __syncthreads();

    // thread t: jj = t&31, part = t>>5 covers c in [part*48, part*48+48)
    {
        const int jj   = tid & 31;
        const int part = tid >> 5;
        float acc = 0.0f;
        #pragma unroll 12
        for (int c = part * 48; c < part * 48 + 48; c++)
            acc = fmaf(s_hist[c], s_w1q[c * 32 + jj], acc);
        s_p[part * 32 + jj] = acc;
    }
    __syncthreads();

    if (tid < 32) {
        const int j = q * 32 + tid;
        float a = s_p[tid] + s_p[32 + tid] + s_p[64 + tid] + s_p[96 + tid]
                + __ldg(params + P_B1 + j);
        g_h1[n * 128 + j] = fmaxf(a, 0.0f);
    }
}

// L2 kernel: 16 blocks (one image), 128 threads. Stages W2 (16 KB) pre-sync.
#define L2_BLOCKS  N_IMG
#define L2_THREADS 128
#define L2_SMEM_FLOATS (4096 + 128 + 128)
#define L2_SMEM_BYTES  (L2_SMEM_FLOATS * 4)       // 17 KB

__global__ __launch_bounds__(L2_THREADS, 1)
void l2_kernel(const float* __restrict__ params, float* __restrict__ out) {
    extern __shared__ float sm2[];
    float* s_w2 = sm2;            // [128][32]
    float* s_h1 = s_w2 + 4096;    // [128]
    float* s_p  = s_h1 + 128;     // [4][32]

    const int tid = threadIdx.x;
    const int n   = blockIdx.x;

    // Pre-sync: stage W2 (overlaps l1/hist)
    #pragma unroll
    for (int i = tid; i < 4096 / 4; i += L2_THREADS)
        reinterpret_cast<float4*>(s_w2)[i] = __ldg(reinterpret_cast<const float4*>(params + P_W2) + i);

    cudaGridDependencySynchronize();

    if (tid < 128) s_h1[tid] = g_h1[n * 128 + tid];
    __syncthreads();

    {
        const int k    = tid & 31;
        const int part = tid >> 5;
        float a = 0.0f;
        #pragma unroll
        for (int c = part * 32; c < part * 32 + 32; c++)
            a = fmaf(s_h1[c], s_w2[c * 32 + k], a);
        s_p[part * 32 + k] = a;
    }
    __syncthreads();

    if (tid < 32) {
        float a = __ldg(params + P_B2 + tid) + __ldg(params + P_G)
                + s_p[tid] + s_p[32 + tid] + s_p[64 + tid] + s_p[96 + tid];
        out[n * 32 + tid] = 1.0f / (1.0f + expf(-a));
    }
}

extern "C" void kernel_launch(void* const* d_in, const int* in_sizes, int n_in,
                              void* d_out, int out_size) {
    const float* img    = (const float*)d_in[0];
    const float* params = (const float*)d_in[1];
    float* out          = (float*)d_out;

    static bool attr_set = false;
    if (!attr_set) {
        cudaFuncSetAttribute(hist_kernel, cudaFuncAttributeMaxDynamicSharedMemorySize, HSMEM_BYTES);
        cudaFuncSetAttribute(l1_kernel,   cudaFuncAttributeMaxDynamicSharedMemorySize, L1_SMEM_BYTES);
        cudaFuncSetAttribute(l2_kernel,   cudaFuncAttributeMaxDynamicSharedMemorySize, L2_SMEM_BYTES);
        attr_set = true;
    }

    hist_kernel<<<NBLOCKS, HTHREADS, HSMEM_BYTES>>>(img);

    cudaLaunchAttribute attrs[1];
    attrs[0].id = cudaLaunchAttributeProgrammaticStreamSerialization;
    attrs[0].val.programmaticStreamSerializationAllowed = 1;

    cudaLaunchConfig_t cfg1 = {};
    cfg1.gridDim  = dim3(L1_BLOCKS, 1, 1);
    cfg1.blockDim = dim3(L1_THREADS, 1, 1);
    cfg1.dynamicSmemBytes = L1_SMEM_BYTES;
    cfg1.attrs = attrs;
    cfg1.numAttrs = 1;
    cudaLaunchKernelEx(&cfg1, l1_kernel, params);

    cudaLaunchConfig_t cfg2 = {};
    cfg2.gridDim  = dim3(L2_BLOCKS, 1, 1);
    cfg2.blockDim = dim3(L2_THREADS, 1, 1);
    cfg2.dynamicSmemBytes = L2_SMEM_BYTES;
    cfg2.attrs = attrs;
    cfg2.numAttrs = 1;
    cudaLaunchKernelEx(&cfg2, l2_kernel, params, out);
}

// round 15
// speedup vs baseline: 1.1896x; 1.0303x over previous
#include <cuda_runtime.h>
#include <math.h>
#include <stdint.h>

// Problem constants
#define N_IMG     16
#define N_CH      3
#define NSLICE    (N_IMG * N_CH)          // 48
#define BINS      64
#define SLICE_ELEMS (1024 * 1024)

#define HTHREADS  128
#define BPS       9                               // 432 blocks (one wave at occ 3)
#define NBLOCKS   (NSLICE * BPS)
// Two u32 counter arrays [64][128] = 32 KB each
#define HSMEM_WORDS (2 * BINS * HTHREADS)
#define HSMEM_BYTES (HSMEM_WORDS * 4)             // 64 KB

// Params layout (in_ch,out_ch row-major), per reference
#define P_W1 0
#define P_B1 24576
#define P_W2 24704
#define P_B2 28800
#define P_G  28832

#define DEPTH 12

__device__ float g_part[NBLOCKS * BINS];

__global__ __launch_bounds__(HTHREADS, 3)
void hist_kernel(const float* __restrict__ img) {
    extern __shared__ unsigned int hh[];   // A = hh[0..8191], B = hh[8192..16383]
    const int tid = threadIdx.x;

    const int slice = blockIdx.x / BPS;
    const int chunk = blockIdx.x % BPS;
    const float4* base = reinterpret_cast<const float4*>(img + (size_t)slice * SLICE_ELEMS);
    const int n4   = SLICE_ELEMS / 4;                 // 262144
    const int per  = (n4 + BPS - 1) / BPS;            // 29128
    const int start = chunk * per;
    const int end   = min(start + per, n4);

    // ---- Prefetch FIRST batch before zeroing: loads fly during the prolog ----
    int i = start + tid;
    float4 A[DEPTH], B[DEPTH];
    bool hasA = (i + (DEPTH - 1) * HTHREADS < end);
    if (hasA) {
        #pragma unroll
        for (int u = 0; u < DEPTH; u++) A[u] = __ldcs(base + i + u * HTHREADS);
    }

    {
        uint4* z = reinterpret_cast<uint4*>(hh);
        #pragma unroll
        for (int q = tid; q < HSMEM_WORDS / 4; q += HTHREADS)
            z[q] = make_uint4(0u, 0u, 0u, 0u);
    }
    __syncthreads();

    unsigned int* pA = hh + tid;                       // A[b][tid] at pA[b*128]
    unsigned int* pB = hh + BINS * HTHREADS + tid;     // B[b][tid] at pB[b*128]

#define PROCPAIR(vA, vB) { \
        int ba = (int)__fmul_rd((vA), 64.0f); \
        int bb = (int)__fmul_rd((vB), 64.0f); \
        unsigned int ca = pA[ba * HTHREADS]; \
        unsigned int cb = pB[bb * HTHREADS]; \
        pA[ba * HTHREADS] = ca + 1u; \
        pB[bb * HTHREADS] = cb + 1u; }
#define PROC(v4) { PROCPAIR((v4).x, (v4).y); PROCPAIR((v4).z, (v4).w); }

    while (hasA) {
        const int j = i + DEPTH * HTHREADS;
        const bool hasB = (j + (DEPTH - 1) * HTHREADS < end);
        if (hasB) {
            #pragma unroll
            for (int u = 0; u < DEPTH; u++) B[u] = __ldcs(base + j + u * HTHREADS);
        }
        #pragma unroll
        for (int u = 0; u < DEPTH; u++) PROC(A[u]);
        i = j;
        if (!hasB) break;
        const int k = j + DEPTH * HTHREADS;
        hasA = (k + (DEPTH - 1) * HTHREADS < end);
        if (hasA) {
            #pragma unroll
            for (int u = 0; u < DEPTH; u++) A[u] = __ldcs(base + k + u * HTHREADS);
        }
        #pragma unroll
        for (int u = 0; u < DEPTH; u++) PROC(B[u]);
        i = k;
    }
    for (; i < end; i += HTHREADS) {
        float4 a = __ldcs(base + i);
        PROC(a);
    }
#undef PROC
#undef PROCPAIR
    __syncthreads();

    // Epilogue: warp w (of 4) reduces bins 16w..16w+15 over 128 columns x 2 arrays.
    const int wid  = tid >> 5;
    const int lane = tid & 31;
    #pragma unroll
    for (int r = 0; r < 16; r++) {
        const int b = wid * 16 + r;
        const unsigned int* ra = hh + b * HTHREADS;
        const unsigned int* rb = hh + BINS * HTHREADS + b * HTHREADS;
        unsigned int s = ra[lane] + ra[lane + 32] + ra[lane + 64] + ra[lane + 96]
                       + rb[lane] + rb[lane + 32] + rb[lane + 64] + rb[lane + 96];
        #pragma unroll
        for (int d = 16; d >= 1; d >>= 1)
            s += __shfl_down_sync(0xFFFFFFFFu, s, d);
        if (lane == 0)
            g_part[blockIdx.x * BINS + b] = (float)s;
    }
}

// MLP with PDL: grid=16 (one image per block), 256 threads (R11 proven config).
#define MLP_BLOCKS  16
#define MLP_THREADS 256
#define MLP_SMEM_FLOATS (24576 + 4096 + 192 + 256 + 128 + 128)
#define MLP_SMEM_BYTES  (MLP_SMEM_FLOATS * 4)

__global__ __launch_bounds__(MLP_THREADS, 1)
void mlp_kernel(const float* __restrict__ params, float* __restrict__ out) {
    extern __shared__ float smem[];
    float* s_w1   = smem;                 // [192][128]
    float* s_w2   = s_w1 + 24576;         // [128][32]
    float* s_hist = s_w2 + 4096;          // [192]
    float* s_p1   = s_hist + 192;         // [2][128]
    float* s_h1   = s_p1 + 256;           // [128]
    float* s_l2   = s_h1 + 128;           // [4][32]

    const int tid = threadIdx.x;
    const int n   = blockIdx.x;

    // Pre-sync: stage weights (overlaps with hist via PDL)
    #pragma unroll
    for (int i = tid; i < 24576 / 4; i += MLP_THREADS)
        reinterpret_cast<float4*>(s_w1)[i] = reinterpret_cast<const float4*>(params + P_W1)[i];
    #pragma unroll
    for (int i = tid; i < 4096 / 4; i += MLP_THREADS)
        reinterpret_cast<float4*>(s_w2)[i] = reinterpret_cast<const float4*>(params + P_W2)[i];

    cudaGridDependencySynchronize();

    if (tid < 192) {
        int c = tid >> 6;
        int b = tid & 63;
        const float* p = g_part + ((n * 3 + c) * BPS) * BINS + b;
        float s = 0.0f;
        #pragma unroll
        for (int k = 0; k < BPS; k++) s += p[k * BINS];
        s_hist[tid] = s;
    }
    __syncthreads();

    {
        const int j    = tid & 127;
        const int half = tid >> 7;
        const int c0   = half * 96;
        float acc = 0.0f;
        #pragma unroll 16
        for (int c = c0; c < c0 + 96; c++)
            acc = fmaf(s_hist[c], s_w1[c * 128 + j], acc);
        s_p1[half * 128 + j] = acc;
    }
    __syncthreads();
    if (tid < 128)
        s_h1[tid] = fmaxf(s_p1[tid] + s_p1[128 + tid] + params[P_B1 + tid], 0.0f);
    __syncthreads();

    if (tid < 128) {
        const int q = tid >> 5;
        const int k = tid & 31;
        float a = 0.0f;
        #pragma unroll
        for (int c = q * 32; c < q * 32 + 32; c++)
            a = fmaf(s_h1[c], s_w2[c * 32 + k], a);
        s_l2[tid] = a;
    }
    __syncthreads();

    if (tid < 32) {
        float a = params[P_B2 + tid] + params[P_G]
                + s_l2[tid] + s_l2[32 + tid] + s_l2[64 + tid] + s_l2[96 + tid];
        out[n * 32 + tid] = 1.0f / (1.0f + expf(-a));
    }
}

extern "C" void kernel_launch(void* const* d_in, const int* in_sizes, int n_in,
                              void* d_out, int out_size) {
    const float* img    = (const float*)d_in[0];
    const float* params = (const float*)d_in[1];
    float* out          = (float*)d_out;

    static bool attr_set = false;
    if (!attr_set) {
        cudaFuncSetAttribute(hist_kernel, cudaFuncAttributeMaxDynamicSharedMemorySize, HSMEM_BYTES);
        cudaFuncSetAttribute(mlp_kernel,  cudaFuncAttributeMaxDynamicSharedMemorySize, MLP_SMEM_BYTES);
        attr_set = true;
    }

    hist_kernel<<<NBLOCKS, HTHREADS, HSMEM_BYTES>>>(img);

    cudaLaunchConfig_t cfg = {};
    cfg.gridDim  = dim3(MLP_BLOCKS, 1, 1);
    cfg.blockDim = dim3(MLP_THREADS, 1, 1);
    cfg.dynamicSmemBytes = MLP_SMEM_BYTES;
    cudaLaunchAttribute attrs[1];
    attrs[0].id = cudaLaunchAttributeProgrammaticStreamSerialization;
    attrs[0].val.programmaticStreamSerializationAllowed = 1;
    cfg.attrs = attrs;
    cfg.numAttrs = 1;
    cudaLaunchKernelEx(&cfg, mlp_kernel, params, out);
}

// round 16
// speedup vs baseline: 1.2412x; 1.0434x over previous
#include <cuda_runtime.h>
#include <math.h>
#include <stdint.h>

// Problem constants
#define N_IMG     16
#define N_CH      3
#define NSLICE    (N_IMG * N_CH)          // 48
#define BINS      64
#define SLICE_ELEMS (1024 * 1024)

#define HTHREADS  128
#define BPS       9                               // 432 blocks (one wave at occ 3)
#define NBLOCKS   (NSLICE * BPS)
// Two u32 counter arrays [64][128] = 32 KB each
#define HSMEM_WORDS (2 * BINS * HTHREADS)
#define HSMEM_BYTES (HSMEM_WORDS * 4)             // 64 KB

// Params layout (in_ch,out_ch row-major), per reference
#define P_W1 0
#define P_B1 24576
#define P_W2 24704
#define P_B2 28800
#define P_G  28832
#define P_TOTAL 28833

#define DEPTH 8
#define WARM_BLOCKS 16

__device__ float g_part[NBLOCKS * BINS];
__device__ float g_sink;   // DCE-guard target for the L2 warmer (never actually written)

__global__ __launch_bounds__(HTHREADS, 3)
void hist_kernel(const float* __restrict__ img, const float* __restrict__ params) {
    extern __shared__ unsigned int hh[];   // A = hh[0..8191], B = hh[8192..16383]
    const int tid = threadIdx.x;

    const int slice = blockIdx.x / BPS;
    const int chunk = blockIdx.x % BPS;
    const float4* base = reinterpret_cast<const float4*>(img + (size_t)slice * SLICE_ELEMS);
    const int n4   = SLICE_ELEMS / 4;                 // 262144
    const int per  = (n4 + BPS - 1) / BPS;            // 29128
    const int start = chunk * per;
    const int end   = min(start + per, n4);

    // ---- Prefetch FIRST batch before zeroing: loads fly during the prolog ----
    int i = start + tid;
    float4 A[DEPTH], B[DEPTH];
    bool hasA = (i + (DEPTH - 1) * HTHREADS < end);
    if (hasA) {
        #pragma unroll
        for (int u = 0; u < DEPTH; u++) A[u] = __ldcs(base + i + u * HTHREADS);
    }

    // ---- First 16 blocks: warm L2 with params for the PDL mlp kernel ----
    // 1/16th of 113 KB each; loads overlap the prolog, result kept alive by an
    // opaque never-true guard so ptxas can't DCE them.
    if (blockIdx.x < WARM_BLOCKS) {
        const int seg   = (P_TOTAL + WARM_BLOCKS - 1) / WARM_BLOCKS;   // 1803
        const int s0    = blockIdx.x * seg;
        const int s1    = min(s0 + seg, P_TOTAL);
        float acc = 0.0f;
        for (int p = s0 + tid; p < s1; p += HTHREADS)
            acc += __ldg(params + p);
        if (__float_as_uint(acc) == 0x7F800001u)   // signaling-NaN pattern: never true
            g_sink = acc;
    }

    {
        uint4* z = reinterpret_cast<uint4*>(hh);
        #pragma unroll
        for (int q = tid; q < HSMEM_WORDS / 4; q += HTHREADS)
            z[q] = make_uint4(0u, 0u, 0u, 0u);
    }
    __syncthreads();

    unsigned int* pA = hh + tid;                       // A[b][tid] at pA[b*128]
    unsigned int* pB = hh + BINS * HTHREADS + tid;     // B[b][tid] at pB[b*128]

#define PROCPAIR(vA, vB) { \
        int ba = (int)__fmul_rd((vA), 64.0f); \
        int bb = (int)__fmul_rd((vB), 64.0f); \
        unsigned int ca = pA[ba * HTHREADS]; \
        unsigned int cb = pB[bb * HTHREADS]; \
        pA[ba * HTHREADS] = ca + 1u; \
        pB[bb * HTHREADS] = cb + 1u; }
#define PROC(v4) { PROCPAIR((v4).x, (v4).y); PROCPAIR((v4).z, (v4).w); }

    while (hasA) {
        const int j = i + DEPTH * HTHREADS;
        const bool hasB = (j + (DEPTH - 1) * HTHREADS < end);
        if (hasB) {
            #pragma unroll
            for (int u = 0; u < DEPTH; u++) B[u] = __ldcs(base + j + u * HTHREADS);
        }
        #pragma unroll
        for (int u = 0; u < DEPTH; u++) PROC(A[u]);
        i = j;
        if (!hasB) break;
        const int k = j + DEPTH * HTHREADS;
        hasA = (k + (DEPTH - 1) * HTHREADS < end);
        if (hasA) {
            #pragma unroll
            for (int u = 0; u < DEPTH; u++) A[u] = __ldcs(base + k + u * HTHREADS);
        }
        #pragma unroll
        for (int u = 0; u < DEPTH; u++) PROC(B[u]);
        i = k;
    }
    for (; i < end; i += HTHREADS) {
        float4 a = __ldcs(base + i);
        PROC(a);
    }
#undef PROC
#undef PROCPAIR
    __syncthreads();

    // Epilogue: warp w (of 4) reduces bins 16w..16w+15 over 128 columns x 2 arrays.
    const int wid  = tid >> 5;
    const int lane = tid & 31;
    #pragma unroll
    for (int r = 0; r < 16; r++) {
        const int b = wid * 16 + r;
        const unsigned int* ra = hh + b * HTHREADS;
        const unsigned int* rb = hh + BINS * HTHREADS + b * HTHREADS;
        unsigned int s = ra[lane] + ra[lane + 32] + ra[lane + 64] + ra[lane + 96]
                       + rb[lane] + rb[lane + 32] + rb[lane + 64] + rb[lane + 96];
        #pragma unroll
        for (int d = 16; d >= 1; d >>= 1)
            s += __shfl_down_sync(0xFFFFFFFFu, s, d);
        if (lane == 0)
            g_part[blockIdx.x * BINS + b] = (float)s;
    }
}

// MLP with PDL: grid=16 (one image per block), 256 threads (R11 proven config).
// Weight staging now hits L2 thanks to the hist-side warmer.
#define MLP_BLOCKS  16
#define MLP_THREADS 256
#define MLP_SMEM_FLOATS (24576 + 4096 + 192 + 256 + 128 + 128)
#define MLP_SMEM_BYTES  (MLP_SMEM_FLOATS * 4)

__global__ __launch_bounds__(MLP_THREADS, 1)
void mlp_kernel(const float* __restrict__ params, float* __restrict__ out) {
    extern __shared__ float smem[];
    float* s_w1   = smem;                 // [192][128]
    float* s_w2   = s_w1 + 24576;         // [128][32]
    float* s_hist = s_w2 + 4096;          // [192]
    float* s_p1   = s_hist + 192;         // [2][128]
    float* s_h1   = s_p1 + 256;           // [128]
    float* s_l2   = s_h1 + 128;           // [4][32]

    const int tid = threadIdx.x;
    const int n   = blockIdx.x;

    // Pre-sync: stage weights (L2-warm; overlaps any hist drain via PDL)
    #pragma unroll
    for (int i = tid; i < 24576 / 4; i += MLP_THREADS)
        reinterpret_cast<float4*>(s_w1)[i] = reinterpret_cast<const float4*>(params + P_W1)[i];
    #pragma unroll
    for (int i = tid; i < 4096 / 4; i += MLP_THREADS)
        reinterpret_cast<float4*>(s_w2)[i] = reinterpret_cast<const float4*>(params + P_W2)[i];

    cudaGridDependencySynchronize();

    if (tid < 192) {
        int c = tid >> 6;
        int b = tid & 63;
        const float* p = g_part + ((n * 3 + c) * BPS) * BINS + b;
        float s = 0.0f;
        #pragma unroll
        for (int k = 0; k < BPS; k++) s += p[k * BINS];
        s_hist[tid] = s;
    }
    __syncthreads();

    {
        const int j    = tid & 127;
        const int half = tid >> 7;
        const int c0   = half * 96;
        float acc = 0.0f;
        #pragma unroll 16
        for (int c = c0; c < c0 + 96; c++)
            acc = fmaf(s_hist[c], s_w1[c * 128 + j], acc);
        s_p1[half * 128 + j] = acc;
    }
    __syncthreads();
    if (tid < 128)
        s_h1[tid] = fmaxf(s_p1[tid] + s_p1[128 + tid] + params[P_B1 + tid], 0.0f);
    __syncthreads();

    if (tid < 128) {
        const int q = tid >> 5;
        const int k = tid & 31;
        float a = 0.0f;
        #pragma unroll
        for (int c = q * 32; c < q * 32 + 32; c++)
            a = fmaf(s_h1[c], s_w2[c * 32 + k], a);
        s_l2[tid] = a;
    }
    __syncthreads();

    if (tid < 32) {
        float a = params[P_B2 + tid] + params[P_G]
                + s_l2[tid] + s_l2[32 + tid] + s_l2[64 + tid] + s_l2[96 + tid];
        out[n * 32 + tid] = 1.0f / (1.0f + expf(-a));
    }
}

extern "C" void kernel_launch(void* const* d_in, const int* in_sizes, int n_in,
                              void* d_out, int out_size) {
    const float* img    = (const float*)d_in[0];
    const float* params = (const float*)d_in[1];
    float* out          = (float*)d_out;

    static bool attr_set = false;
    if (!attr_set) {
        cudaFuncSetAttribute(hist_kernel, cudaFuncAttributeMaxDynamicSharedMemorySize, HSMEM_BYTES);
        cudaFuncSetAttribute(mlp_kernel,  cudaFuncAttributeMaxDynamicSharedMemorySize, MLP_SMEM_BYTES);
        attr_set = true;
    }

    hist_kernel<<<NBLOCKS, HTHREADS, HSMEM_BYTES>>>(img, params);

    cudaLaunchConfig_t cfg = {};
    cfg.gridDim  = dim3(MLP_BLOCKS, 1, 1);
    cfg.blockDim = dim3(MLP_THREADS, 1, 1);
    cfg.dynamicSmemBytes = MLP_SMEM_BYTES;
    cudaLaunchAttribute attrs[1];
    attrs[0].id = cudaLaunchAttributeProgrammaticStreamSerialization;
    attrs[0].val.programmaticStreamSerializationAllowed = 1;
    cfg.attrs = attrs;
    cfg.numAttrs = 1;
    cudaLaunchKernelEx(&cfg, mlp_kernel, params, out);
}